// round 5
// baseline (speedup 1.0000x reference)
#include <cuda_runtime.h>
#include <math.h>

// Problem constants (fixed shapes from reference: B=4, S=2048, H=1024, O=512)
#define BATCH 4
#define SEQ   2048
#define HID   1024
#define OUT   512

// ---------------------------------------------------------------------------
// Device scratch (static __device__ arrays: allowed; no runtime allocation)
// ---------------------------------------------------------------------------
__device__ float g_scores[(size_t)BATCH * SEQ * SEQ];   // 64 MB
__device__ float g_ct[(size_t)BATCH * SEQ * HID];       // 32 MB
__device__ float g_lam[BATCH * SEQ];                    // 32 KB

// ---------------------------------------------------------------------------
// Kernel 1: lambda gate  lam[row] = sigmoid(ho_row . W_lambda + b_lambda)
// one block (256 thr) per row; each thread handles exactly 4 elements (float4)
// ---------------------------------------------------------------------------
__global__ __launch_bounds__(256)
void k_lambda(const float* __restrict__ ho,
              const float* __restrict__ Wl,
              const float* __restrict__ bl)
{
    const int row = blockIdx.x;                 // 0 .. BATCH*SEQ-1
    const int t   = threadIdx.x;                // 0 .. 255
    const float4 xv = reinterpret_cast<const float4*>(ho + (size_t)row * HID)[t];
    const float4 wv = reinterpret_cast<const float4*>(Wl)[t];
    float s = xv.x * wv.x + xv.y * wv.y + xv.z * wv.z + xv.w * wv.w;

    // warp reduce
    #pragma unroll
    for (int o = 16; o > 0; o >>= 1)
        s += __shfl_xor_sync(0xFFFFFFFFu, s, o);

    __shared__ float sm[8];
    if ((t & 31) == 0) sm[t >> 5] = s;
    __syncthreads();
    if (t == 0) {
        float tot = 0.f;
        #pragma unroll
        for (int i = 0; i < 8; i++) tot += sm[i];
        tot += bl[0];
        g_lam[row] = 1.f / (1.f + expf(-tot));
    }
}

// ---------------------------------------------------------------------------
// Kernel 2: scores = (1/32) * ho · hi^T   (per batch; NT GEMM, M=N=2048, K=1024)
// 128x128 tile, BK=8, 256 threads, 8x8 microtile
// ---------------------------------------------------------------------------
__global__ __launch_bounds__(256, 2)
void k_scores(const float* __restrict__ ho, const float* __restrict__ hi)
{
    const int b = blockIdx.z;
    const float* A = ho + (size_t)b * SEQ * HID;   // [SEQ, HID] row-major
    const float* Bm = hi + (size_t)b * SEQ * HID;  // [SEQ, HID] row-major
    float* C = g_scores + (size_t)b * SEQ * SEQ;   // [SEQ, SEQ]

    __shared__ float As[8][132];   // +4 pad: conflict-free, keeps 16B alignment
    __shared__ float Bs[8][132];

    const int tid = threadIdx.x;
    const int tx = tid & 15, ty = tid >> 4;
    const int m0 = blockIdx.y * 128, n0 = blockIdx.x * 128;
    const int lr = tid >> 1;             // 0..127 (row within tile)
    const int lq = (tid & 1) << 2;       // 0 or 4 (k-quad)

    const float* Aptr = A + (size_t)(m0 + lr) * HID + lq;
    const float* Bptr = Bm + (size_t)(n0 + lr) * HID + lq;

    float acc[8][8];
    #pragma unroll
    for (int i = 0; i < 8; i++)
        #pragma unroll
        for (int j = 0; j < 8; j++) acc[i][j] = 0.f;

    for (int k0 = 0; k0 < HID; k0 += 8) {
        const float4 av = *reinterpret_cast<const float4*>(Aptr + k0);
        const float4 bv = *reinterpret_cast<const float4*>(Bptr + k0);
        As[lq + 0][lr] = av.x; As[lq + 1][lr] = av.y;
        As[lq + 2][lr] = av.z; As[lq + 3][lr] = av.w;
        Bs[lq + 0][lr] = bv.x; Bs[lq + 1][lr] = bv.y;
        Bs[lq + 2][lr] = bv.z; Bs[lq + 3][lr] = bv.w;
        __syncthreads();
        #pragma unroll
        for (int k = 0; k < 8; k++) {
            const float4 a0 = *reinterpret_cast<const float4*>(&As[k][ty << 2]);
            const float4 a1 = *reinterpret_cast<const float4*>(&As[k][64 + (ty << 2)]);
            const float4 b0 = *reinterpret_cast<const float4*>(&Bs[k][tx << 2]);
            const float4 b1 = *reinterpret_cast<const float4*>(&Bs[k][64 + (tx << 2)]);
            const float a[8]  = {a0.x, a0.y, a0.z, a0.w, a1.x, a1.y, a1.z, a1.w};
            const float bb[8] = {b0.x, b0.y, b0.z, b0.w, b1.x, b1.y, b1.z, b1.w};
            #pragma unroll
            for (int i = 0; i < 8; i++)
                #pragma unroll
                for (int j = 0; j < 8; j++) acc[i][j] += a[i] * bb[j];
        }
        __syncthreads();
    }

    const float scale = 0.03125f;   // 1/sqrt(1024)
    #pragma unroll
    for (int i = 0; i < 4; i++) {
        const int r0 = m0 + (ty << 2) + i;
        const int r1 = r0 + 64;
        float4 c;
        c.x = acc[i][0] * scale; c.y = acc[i][1] * scale;
        c.z = acc[i][2] * scale; c.w = acc[i][3] * scale;
        *reinterpret_cast<float4*>(&C[(size_t)r0 * SEQ + n0 + (tx << 2)]) = c;
        c.x = acc[i][4] * scale; c.y = acc[i][5] * scale;
        c.z = acc[i][6] * scale; c.w = acc[i][7] * scale;
        *reinterpret_cast<float4*>(&C[(size_t)r0 * SEQ + n0 + 64 + (tx << 2)]) = c;
        c.x = acc[4 + i][0] * scale; c.y = acc[4 + i][1] * scale;
        c.z = acc[4 + i][2] * scale; c.w = acc[4 + i][3] * scale;
        *reinterpret_cast<float4*>(&C[(size_t)r1 * SEQ + n0 + (tx << 2)]) = c;
        c.x = acc[4 + i][4] * scale; c.y = acc[4 + i][5] * scale;
        c.z = acc[4 + i][6] * scale; c.w = acc[4 + i][7] * scale;
        *reinterpret_cast<float4*>(&C[(size_t)r1 * SEQ + n0 + 64 + (tx << 2)]) = c;
    }
}

// ---------------------------------------------------------------------------
// Kernel 3: row softmax over scores (8192 rows of 2048)
// ---------------------------------------------------------------------------
__global__ __launch_bounds__(256)
void k_softmax()
{
    float* p = g_scores + (size_t)blockIdx.x * SEQ;
    const int t = threadIdx.x;
    float4 v0 = reinterpret_cast<float4*>(p)[t];
    float4 v1 = reinterpret_cast<float4*>(p)[t + 256];

    float m = fmaxf(fmaxf(fmaxf(v0.x, v0.y), fmaxf(v0.z, v0.w)),
                    fmaxf(fmaxf(v1.x, v1.y), fmaxf(v1.z, v1.w)));
    #pragma unroll
    for (int o = 16; o > 0; o >>= 1)
        m = fmaxf(m, __shfl_xor_sync(0xFFFFFFFFu, m, o));

    __shared__ float sm[8];
    if ((t & 31) == 0) sm[t >> 5] = m;
    __syncthreads();
    m = sm[0];
    #pragma unroll
    for (int i = 1; i < 8; i++) m = fmaxf(m, sm[i]);
    __syncthreads();   // before sm reuse

    v0.x = expf(v0.x - m); v0.y = expf(v0.y - m);
    v0.z = expf(v0.z - m); v0.w = expf(v0.w - m);
    v1.x = expf(v1.x - m); v1.y = expf(v1.y - m);
    v1.z = expf(v1.z - m); v1.w = expf(v1.w - m);

    float s = (v0.x + v0.y + v0.z + v0.w) + (v1.x + v1.y + v1.z + v1.w);
    #pragma unroll
    for (int o = 16; o > 0; o >>= 1)
        s += __shfl_xor_sync(0xFFFFFFFFu, s, o);
    if ((t & 31) == 0) sm[t >> 5] = s;
    __syncthreads();
    s = sm[0];
    #pragma unroll
    for (int i = 1; i < 8; i++) s += sm[i];

    const float inv = 1.f / s;
    v0.x *= inv; v0.y *= inv; v0.z *= inv; v0.w *= inv;
    v1.x *= inv; v1.y *= inv; v1.z *= inv; v1.w *= inv;
    reinterpret_cast<float4*>(p)[t]       = v0;
    reinterpret_cast<float4*>(p)[t + 256] = v1;
}

// ---------------------------------------------------------------------------
// Kernel 4: attended = attn · hi, fused gate:
//   ct = lam*ho + (1-lam)*attended     (per batch; NN GEMM M=2048,N=1024,K=2048)
// ---------------------------------------------------------------------------
__global__ __launch_bounds__(256, 2)
void k_attend(const float* __restrict__ hi, const float* __restrict__ ho)
{
    const int b = blockIdx.z;
    const float* A  = g_scores + (size_t)b * SEQ * SEQ;   // attn [SEQ, SEQ]
    const float* Bm = hi + (size_t)b * SEQ * HID;         // [SEQ(K), HID(N)]
    const float* hoB = ho + (size_t)b * SEQ * HID;
    const float* lamB = g_lam + b * SEQ;
    float* C = g_ct + (size_t)b * SEQ * HID;

    __shared__ float As[8][132];
    __shared__ float Bs[8][132];

    const int tid = threadIdx.x;
    const int tx = tid & 15, ty = tid >> 4;
    const int m0 = blockIdx.y * 128, n0 = blockIdx.x * 128;
    const int lr = tid >> 1;
    const int lq = (tid & 1) << 2;
    const int brow = tid >> 5;               // 0..7
    const int bcol = (tid & 31) << 2;        // 0..124

    const float* Aptr = A + (size_t)(m0 + lr) * SEQ + lq;
    const float* Bptr = Bm + (size_t)brow * HID + n0 + bcol;

    float acc[8][8];
    #pragma unroll
    for (int i = 0; i < 8; i++)
        #pragma unroll
        for (int j = 0; j < 8; j++) acc[i][j] = 0.f;

    for (int k0 = 0; k0 < SEQ; k0 += 8) {
        const float4 av = *reinterpret_cast<const float4*>(Aptr + k0);
        const float4 bv = *reinterpret_cast<const float4*>(Bptr + (size_t)k0 * HID);
        As[lq + 0][lr] = av.x; As[lq + 1][lr] = av.y;
        As[lq + 2][lr] = av.z; As[lq + 3][lr] = av.w;
        *reinterpret_cast<float4*>(&Bs[brow][bcol]) = bv;
        __syncthreads();
        #pragma unroll
        for (int k = 0; k < 8; k++) {
            const float4 a0 = *reinterpret_cast<const float4*>(&As[k][ty << 2]);
            const float4 a1 = *reinterpret_cast<const float4*>(&As[k][64 + (ty << 2)]);
            const float4 b0 = *reinterpret_cast<const float4*>(&Bs[k][tx << 2]);
            const float4 b1 = *reinterpret_cast<const float4*>(&Bs[k][64 + (tx << 2)]);
            const float a[8]  = {a0.x, a0.y, a0.z, a0.w, a1.x, a1.y, a1.z, a1.w};
            const float bb[8] = {b0.x, b0.y, b0.z, b0.w, b1.x, b1.y, b1.z, b1.w};
            #pragma unroll
            for (int i = 0; i < 8; i++)
                #pragma unroll
                for (int j = 0; j < 8; j++) acc[i][j] += a[i] * bb[j];
        }
        __syncthreads();
    }

    #pragma unroll
    for (int i = 0; i < 4; i++) {
        const int r0 = m0 + (ty << 2) + i;
        const int r1 = r0 + 64;
        const float l0 = lamB[r0], g0 = 1.f - l0;
        const float l1 = lamB[r1], g1 = 1.f - l1;
        const float4 h00 = *reinterpret_cast<const float4*>(&hoB[(size_t)r0 * HID + n0 + (tx << 2)]);
        const float4 h01 = *reinterpret_cast<const float4*>(&hoB[(size_t)r0 * HID + n0 + 64 + (tx << 2)]);
        const float4 h10 = *reinterpret_cast<const float4*>(&hoB[(size_t)r1 * HID + n0 + (tx << 2)]);
        const float4 h11 = *reinterpret_cast<const float4*>(&hoB[(size_t)r1 * HID + n0 + 64 + (tx << 2)]);
        float4 c;
        c.x = l0 * h00.x + g0 * acc[i][0]; c.y = l0 * h00.y + g0 * acc[i][1];
        c.z = l0 * h00.z + g0 * acc[i][2]; c.w = l0 * h00.w + g0 * acc[i][3];
        *reinterpret_cast<float4*>(&C[(size_t)r0 * HID + n0 + (tx << 2)]) = c;
        c.x = l0 * h01.x + g0 * acc[i][4]; c.y = l0 * h01.y + g0 * acc[i][5];
        c.z = l0 * h01.z + g0 * acc[i][6]; c.w = l0 * h01.w + g0 * acc[i][7];
        *reinterpret_cast<float4*>(&C[(size_t)r0 * HID + n0 + 64 + (tx << 2)]) = c;
        c.x = l1 * h10.x + g1 * acc[4 + i][0]; c.y = l1 * h10.y + g1 * acc[4 + i][1];
        c.z = l1 * h10.z + g1 * acc[4 + i][2]; c.w = l1 * h10.w + g1 * acc[4 + i][3];
        *reinterpret_cast<float4*>(&C[(size_t)r1 * HID + n0 + (tx << 2)]) = c;
        c.x = l1 * h11.x + g1 * acc[4 + i][4]; c.y = l1 * h11.y + g1 * acc[4 + i][5];
        c.z = l1 * h11.z + g1 * acc[4 + i][6]; c.w = l1 * h11.w + g1 * acc[4 + i][7];
        *reinterpret_cast<float4*>(&C[(size_t)r1 * HID + n0 + 64 + (tx << 2)]) = c;
    }
}

// ---------------------------------------------------------------------------
// Kernel 5: out = ct · W_proj + b_proj  (NN GEMM M=8192, N=512, K=1024)
// ---------------------------------------------------------------------------
__global__ __launch_bounds__(256, 2)
void k_proj(const float* __restrict__ Wp, const float* __restrict__ bp,
            float* __restrict__ outp)
{
    const float* A = g_ct;                // [8192, 1024]
    __shared__ float As[8][132];
    __shared__ float Bs[8][132];

    const int tid = threadIdx.x;
    const int tx = tid & 15, ty = tid >> 4;
    const int m0 = blockIdx.y * 128, n0 = blockIdx.x * 128;
    const int lr = tid >> 1;
    const int lq = (tid & 1) << 2;
    const int brow = tid >> 5;
    const int bcol = (tid & 31) << 2;

    const float* Aptr = A + (size_t)(m0 + lr) * HID + lq;
    const float* Bptr = Wp + (size_t)brow * OUT + n0 + bcol;

    float acc[8][8];
    #pragma unroll
    for (int i = 0; i < 8; i++)
        #pragma unroll
        for (int j = 0; j < 8; j++) acc[i][j] = 0.f;

    for (int k0 = 0; k0 < HID; k0 += 8) {
        const float4 av = *reinterpret_cast<const float4*>(Aptr + k0);
        const float4 bv = *reinterpret_cast<const float4*>(Bptr + (size_t)k0 * OUT);
        As[lq + 0][lr] = av.x; As[lq + 1][lr] = av.y;
        As[lq + 2][lr] = av.z; As[lq + 3][lr] = av.w;
        *reinterpret_cast<float4*>(&Bs[brow][bcol]) = bv;
        __syncthreads();
        #pragma unroll
        for (int k = 0; k < 8; k++) {
            const float4 a0 = *reinterpret_cast<const float4*>(&As[k][ty << 2]);
            const float4 a1 = *reinterpret_cast<const float4*>(&As[k][64 + (ty << 2)]);
            const float4 b0 = *reinterpret_cast<const float4*>(&Bs[k][tx << 2]);
            const float4 b1 = *reinterpret_cast<const float4*>(&Bs[k][64 + (tx << 2)]);
            const float a[8]  = {a0.x, a0.y, a0.z, a0.w, a1.x, a1.y, a1.z, a1.w};
            const float bb[8] = {b0.x, b0.y, b0.z, b0.w, b1.x, b1.y, b1.z, b1.w};
            #pragma unroll
            for (int i = 0; i < 8; i++)
                #pragma unroll
                for (int j = 0; j < 8; j++) acc[i][j] += a[i] * bb[j];
        }
        __syncthreads();
    }

    const float4 bp0 = *reinterpret_cast<const float4*>(&bp[n0 + (tx << 2)]);
    const float4 bp1 = *reinterpret_cast<const float4*>(&bp[n0 + 64 + (tx << 2)]);

    #pragma unroll
    for (int i = 0; i < 4; i++) {
        const int r0 = m0 + (ty << 2) + i;
        const int r1 = r0 + 64;
        float4 c;
        c.x = acc[i][0] + bp0.x; c.y = acc[i][1] + bp0.y;
        c.z = acc[i][2] + bp0.z; c.w = acc[i][3] + bp0.w;
        *reinterpret_cast<float4*>(&outp[(size_t)r0 * OUT + n0 + (tx << 2)]) = c;
        c.x = acc[i][4] + bp1.x; c.y = acc[i][5] + bp1.y;
        c.z = acc[i][6] + bp1.z; c.w = acc[i][7] + bp1.w;
        *reinterpret_cast<float4*>(&outp[(size_t)r0 * OUT + n0 + 64 + (tx << 2)]) = c;
        c.x = acc[4 + i][0] + bp0.x; c.y = acc[4 + i][1] + bp0.y;
        c.z = acc[4 + i][2] + bp0.z; c.w = acc[4 + i][3] + bp0.w;
        *reinterpret_cast<float4*>(&outp[(size_t)r1 * OUT + n0 + (tx << 2)]) = c;
        c.x = acc[4 + i][4] + bp1.x; c.y = acc[4 + i][5] + bp1.y;
        c.z = acc[4 + i][6] + bp1.z; c.w = acc[4 + i][7] + bp1.w;
        *reinterpret_cast<float4*>(&outp[(size_t)r1 * OUT + n0 + 64 + (tx << 2)]) = c;
    }
}

// ---------------------------------------------------------------------------
// Launch
// ---------------------------------------------------------------------------
extern "C" void kernel_launch(void* const* d_in, const int* in_sizes, int n_in,
                              void* d_out, int out_size)
{
    const float* ho = (const float*)d_in[0];   // [4, 2048, 1024]
    const float* hi = (const float*)d_in[1];   // [4, 2048, 1024]
    const float* Wl = (const float*)d_in[2];   // [1024, 1]
    const float* bl = (const float*)d_in[3];   // [1]
    const float* Wp = (const float*)d_in[4];   // [1024, 512]
    const float* bp = (const float*)d_in[5];   // [512]
    float* outp = (float*)d_out;               // [4, 2048, 512]

    k_lambda<<<BATCH * SEQ, 256>>>(ho, Wl, bl);

    dim3 g1(SEQ / 128, SEQ / 128, BATCH);      // 16 x 16 x 4
    k_scores<<<g1, 256>>>(ho, hi);

    k_softmax<<<BATCH * SEQ, 256>>>();

    dim3 g2(HID / 128, SEQ / 128, BATCH);      // 8 x 16 x 4
    k_attend<<<g2, 256>>>(hi, ho);

    dim3 g3(OUT / 128, (BATCH * SEQ) / 128, 1);  // 4 x 64
    k_proj<<<g3, 256>>>(Wp, bp, outp);
}

// round 8
// speedup vs baseline: 2.3058x; 2.3058x over previous
#include <cuda_runtime.h>
#include <cuda_bf16.h>
#include <math.h>
#include <stdint.h>

// Problem constants (fixed shapes: B=4, S=2048, H=1024, O=512)
#define BATCH 4
#define SEQ   2048
#define HID   1024
#define OUT   512

// ===========================================================================
// Device scratch
// ===========================================================================
__device__ float g_scores[(size_t)BATCH * SEQ * SEQ];            // 64 MB fp32
__device__ float g_lam[BATCH * SEQ];

__device__ __nv_bfloat16 g_ho_hi[(size_t)BATCH * SEQ * HID];
__device__ __nv_bfloat16 g_ho_lo[(size_t)BATCH * SEQ * HID];
__device__ __nv_bfloat16 g_hi_hi[(size_t)BATCH * SEQ * HID];
__device__ __nv_bfloat16 g_hi_lo[(size_t)BATCH * SEQ * HID];
__device__ __nv_bfloat16 g_hiT_hi[(size_t)BATCH * HID * SEQ];    // hi transposed
__device__ __nv_bfloat16 g_hiT_lo[(size_t)BATCH * HID * SEQ];
__device__ __nv_bfloat16 g_attn_hi[(size_t)BATCH * SEQ * SEQ];
__device__ __nv_bfloat16 g_attn_lo[(size_t)BATCH * SEQ * SEQ];
__device__ __nv_bfloat16 g_ct_hi[(size_t)BATCH * SEQ * HID];
__device__ __nv_bfloat16 g_ct_lo[(size_t)BATCH * SEQ * HID];
__device__ __nv_bfloat16 g_wt_hi[(size_t)OUT * HID];             // W_proj^T
__device__ __nv_bfloat16 g_wt_lo[(size_t)OUT * HID];

// ===========================================================================
// Low-level helpers (all sm_80+ PTX: compiles on compute_100)
// ===========================================================================
__device__ __forceinline__ uint32_t smem_to_u32(const void* p) {
    uint32_t a;
    asm("{ .reg .u64 t; cvta.to.shared.u64 t, %1; cvt.u32.u64 %0, t; }" : "=r"(a) : "l"(p));
    return a;
}
__device__ __forceinline__ uint32_t sw64(uint32_t o) { return o ^ ((o >> 3) & 0x30); }

__device__ __forceinline__ void cp16(uint32_t dst, const void* src) {
    asm volatile("cp.async.cg.shared.global [%0], [%1], 16;" :: "r"(dst), "l"(src));
}
#define CP_COMMIT() asm volatile("cp.async.commit_group;" ::: "memory")
#define CP_WAIT(n)  asm volatile("cp.async.wait_group %0;" :: "n"(n) : "memory")

__device__ __forceinline__ void ldsm4(uint32_t (&r)[4], uint32_t addr) {
    asm volatile("ldmatrix.sync.aligned.m8n8.x4.shared.b16 {%0,%1,%2,%3}, [%4];"
                 : "=r"(r[0]), "=r"(r[1]), "=r"(r[2]), "=r"(r[3]) : "r"(addr));
}
__device__ __forceinline__ void mma16816(float (&d)[4], const uint32_t a[4], const uint32_t b[2]) {
    asm volatile(
        "mma.sync.aligned.m16n8k16.row.col.f32.bf16.bf16.f32 "
        "{%0,%1,%2,%3},{%4,%5,%6,%7},{%8,%9},{%0,%1,%2,%3};"
        : "+f"(d[0]), "+f"(d[1]), "+f"(d[2]), "+f"(d[3])
        : "r"(a[0]), "r"(a[1]), "r"(a[2]), "r"(a[3]), "r"(b[0]), "r"(b[1]));
}

__device__ __forceinline__ uint32_t pack2bf(float a, float b) {
    __nv_bfloat162 t = __floats2bfloat162_rn(a, b);
    return *reinterpret_cast<uint32_t*>(&t);
}
__device__ __forceinline__ void split1(float x, float& hf, float& lf) {
    __nv_bfloat16 h = __float2bfloat16_rn(x);
    hf = __bfloat162float(h);
    lf = x - hf;
}

// ===========================================================================
// GEMM mainloop: CTA tile 128(M) x 128(N), BK=32, 3-stage cp.async pipeline.
// 3-term compensated bf16: acc += Ah*Bh + Ah*Bl + Al*Bh (fp32 accum).
// A: [128 rows, K] K-contiguous; B: [128 n-rows, K] K-contiguous.
// ===========================================================================
#define BK          32
#define NSTAGE      3
#define TILE_BYTES  8192                   // 128 rows x 64B
#define STAGE_BYTES (4 * TILE_BYTES)       // Ah,Al,Bh,Bl = 32 KB
#define OFF_AHI     0
#define OFF_ALO     TILE_BYTES
#define OFF_BHI     (2 * TILE_BYTES)
#define OFF_BLO     (3 * TILE_BYTES)
#define SMEM_TOTAL  (NSTAGE * STAGE_BYTES) // 96 KB

__device__ __forceinline__ void load_stage(uint32_t smem_base, int s,
    const __nv_bfloat16* __restrict__ Ah, const __nv_bfloat16* __restrict__ Al, int ldA,
    const __nv_bfloat16* __restrict__ Bh, const __nv_bfloat16* __restrict__ Bl, int ldB,
    int k0, int tid)
{
    const uint32_t sb = smem_base + (uint32_t)s * STAGE_BYTES;
    #pragma unroll
    for (int i = 0; i < 2; i++) {
        const int idx = tid + i * 256;           // 0..511
        const int r = idx >> 2, c = idx & 3;     // row 0..127, 16B chunk 0..3
        const uint32_t so = sw64((uint32_t)((r << 6) | (c << 4)));
        const size_t ga = (size_t)r * ldA + k0 + c * 8;
        const size_t gb = (size_t)r * ldB + k0 + c * 8;
        cp16(sb + OFF_AHI + so, Ah + ga);
        cp16(sb + OFF_ALO + so, Al + ga);
        cp16(sb + OFF_BHI + so, Bh + gb);
        cp16(sb + OFF_BLO + so, Bl + gb);
    }
}

// acc[mi][ni][4]: warp tile 64(M) x 32(N); warps: wm = wid&1 (M), wn = wid>>1 (N)
__device__ __forceinline__ void gemm_mainloop(uint32_t smem_base,
    const __nv_bfloat16* __restrict__ Ah, const __nv_bfloat16* __restrict__ Al, int ldA,
    const __nv_bfloat16* __restrict__ Bh, const __nv_bfloat16* __restrict__ Bl, int ldB,
    int nchunks, int tid, float (&acc)[4][4][4])
{
    #pragma unroll
    for (int mi = 0; mi < 4; mi++)
        #pragma unroll
        for (int ni = 0; ni < 4; ni++)
            #pragma unroll
            for (int d = 0; d < 4; d++) acc[mi][ni][d] = 0.f;

    // prologue: prefetch stages 0..NSTAGE-2
    #pragma unroll
    for (int s = 0; s < NSTAGE - 1; s++) {
        load_stage(smem_base, s, Ah, Al, ldA, Bh, Bl, ldB, s * BK, tid);
        CP_COMMIT();
    }
    CP_WAIT(NSTAGE - 2);
    __syncthreads();

    const int lane = tid & 31, wid = tid >> 5;
    const int wm = wid & 1, wn = wid >> 1;
    const int quad = lane >> 3, lrow = lane & 7;
    // per-lane ldmatrix row/col-byte (within tile), before swizzle
    const uint32_t a_term = (uint32_t)((wm * 64 + (quad & 1) * 8 + lrow) << 6) + ((quad >> 1) << 4);
    const uint32_t b_term = (uint32_t)((wn * 32 + (quad >> 1) * 8 + lrow) << 6) + ((quad & 1) << 4);

    for (int c = 0; c < nchunks; c++) {
        const uint32_t sb = smem_base + (uint32_t)(c % NSTAGE) * STAGE_BYTES;

        // prefetch chunk c+NSTAGE-1 (stage is free: last read at chunk c-1)
        const int cp = c + NSTAGE - 1;
        if (cp < nchunks)
            load_stage(smem_base, cp % NSTAGE, Ah, Al, ldA, Bh, Bl, ldB, cp * BK, tid);
        CP_COMMIT();

        #pragma unroll
        for (int ks = 0; ks < 2; ks++) {
            const uint32_t koff = (uint32_t)ks * 32;
            uint32_t Ahf[4][4], Alf[4][4];
            #pragma unroll
            for (int mi = 0; mi < 4; mi++) {
                const uint32_t off = sw64(a_term + (uint32_t)(mi << 10) + koff);
                ldsm4(Ahf[mi], sb + OFF_AHI + off);
                ldsm4(Alf[mi], sb + OFF_ALO + off);
            }
            uint32_t Bhf[2][4], Blf[2][4];
            #pragma unroll
            for (int bi = 0; bi < 2; bi++) {
                const uint32_t off = sw64(b_term + (uint32_t)(bi << 10) + koff);
                ldsm4(Bhf[bi], sb + OFF_BHI + off);
                ldsm4(Blf[bi], sb + OFF_BLO + off);
            }
            #pragma unroll
            for (int mi = 0; mi < 4; mi++)
                #pragma unroll
                for (int ni = 0; ni < 4; ni++) {
                    const uint32_t* bh = &Bhf[ni >> 1][(ni & 1) * 2];
                    const uint32_t* bl = &Blf[ni >> 1][(ni & 1) * 2];
                    mma16816(acc[mi][ni], Ahf[mi], bh);
                    mma16816(acc[mi][ni], Ahf[mi], bl);
                    mma16816(acc[mi][ni], Alf[mi], bh);
                }
        }
        CP_WAIT(NSTAGE - 2);
        __syncthreads();
    }
}

// ===========================================================================
// GEMM 1: scores = (1/32) * ho . hi^T   per batch (M=N=2048, K=1024)
// ===========================================================================
__global__ __launch_bounds__(256, 1) void k_scores_tc()
{
    extern __shared__ __align__(1024) char smem[];
    const uint32_t smem_base = smem_to_u32(smem);
    const int tid = threadIdx.x, lane = tid & 31, wid = tid >> 5;
    const int b = blockIdx.z, m0 = blockIdx.y * 128, n0 = blockIdx.x * 128;

    const size_t ab = ((size_t)b * SEQ + m0) * HID;
    const size_t bb = ((size_t)b * SEQ + n0) * HID;
    float acc[4][4][4];
    gemm_mainloop(smem_base, g_ho_hi + ab, g_ho_lo + ab, HID,
                  g_hi_hi + bb, g_hi_lo + bb, HID, HID / BK, tid, acc);

    float* C = g_scores + (size_t)b * SEQ * SEQ;
    const int wm = wid & 1, wn = wid >> 1;
    const int g = lane >> 2, tq = lane & 3;
    #pragma unroll
    for (int mi = 0; mi < 4; mi++) {
        const int r0 = m0 + wm * 64 + mi * 16 + g;
        #pragma unroll
        for (int ni = 0; ni < 4; ni++) {
            const int col = n0 + wn * 32 + ni * 8 + tq * 2;
            float2 p;
            p.x = acc[mi][ni][0] * 0.03125f; p.y = acc[mi][ni][1] * 0.03125f;
            *reinterpret_cast<float2*>(&C[(size_t)r0 * SEQ + col]) = p;
            p.x = acc[mi][ni][2] * 0.03125f; p.y = acc[mi][ni][3] * 0.03125f;
            *reinterpret_cast<float2*>(&C[(size_t)(r0 + 8) * SEQ + col]) = p;
        }
    }
}

// ===========================================================================
// GEMM 2: attended = attn . hi (via hiT) + fused gate -> ct (bf16 hi/lo)
//   per batch: M=2048, N=1024, K=2048
// ===========================================================================
__global__ __launch_bounds__(256, 1) void k_attend_tc(const float* __restrict__ ho)
{
    extern __shared__ __align__(1024) char smem[];
    const uint32_t smem_base = smem_to_u32(smem);
    const int tid = threadIdx.x, lane = tid & 31, wid = tid >> 5;
    const int b = blockIdx.z, m0 = blockIdx.y * 128, n0 = blockIdx.x * 128;

    const size_t ab = (size_t)b * SEQ * SEQ + (size_t)m0 * SEQ;
    const size_t bb = (size_t)b * HID * SEQ + (size_t)n0 * SEQ;
    float acc[4][4][4];
    gemm_mainloop(smem_base, g_attn_hi + ab, g_attn_lo + ab, SEQ,
                  g_hiT_hi + bb, g_hiT_lo + bb, SEQ, SEQ / BK, tid, acc);

    const int wm = wid & 1, wn = wid >> 1;
    const int g = lane >> 2, tq = lane & 3;
    const float* lamB = g_lam + b * SEQ;
    #pragma unroll
    for (int mi = 0; mi < 4; mi++) {
        const int r0 = m0 + wm * 64 + mi * 16 + g;
        const int r1 = r0 + 8;
        const float l0 = lamB[r0], gl0 = 1.f - l0;
        const float l1 = lamB[r1], gl1 = 1.f - l1;
        const float* hoR0 = ho + ((size_t)b * SEQ + r0) * HID;
        const float* hoR1 = ho + ((size_t)b * SEQ + r1) * HID;
        __nv_bfloat16* CH0 = g_ct_hi + ((size_t)b * SEQ + r0) * HID;
        __nv_bfloat16* CL0 = g_ct_lo + ((size_t)b * SEQ + r0) * HID;
        __nv_bfloat16* CH1 = g_ct_hi + ((size_t)b * SEQ + r1) * HID;
        __nv_bfloat16* CL1 = g_ct_lo + ((size_t)b * SEQ + r1) * HID;
        #pragma unroll
        for (int ni = 0; ni < 4; ni++) {
            const int col = n0 + wn * 32 + ni * 8 + tq * 2;
            {
                const float2 h = *reinterpret_cast<const float2*>(&hoR0[col]);
                const float c0 = l0 * h.x + gl0 * acc[mi][ni][0];
                const float c1 = l0 * h.y + gl0 * acc[mi][ni][1];
                float h0, lo0, h1, lo1;
                split1(c0, h0, lo0); split1(c1, h1, lo1);
                *reinterpret_cast<uint32_t*>(&CH0[col]) = pack2bf(h0, h1);
                *reinterpret_cast<uint32_t*>(&CL0[col]) = pack2bf(lo0, lo1);
            }
            {
                const float2 h = *reinterpret_cast<const float2*>(&hoR1[col]);
                const float c0 = l1 * h.x + gl1 * acc[mi][ni][2];
                const float c1 = l1 * h.y + gl1 * acc[mi][ni][3];
                float h0, lo0, h1, lo1;
                split1(c0, h0, lo0); split1(c1, h1, lo1);
                *reinterpret_cast<uint32_t*>(&CH1[col]) = pack2bf(h0, h1);
                *reinterpret_cast<uint32_t*>(&CL1[col]) = pack2bf(lo0, lo1);
            }
        }
    }
}

// ===========================================================================
// GEMM 3: out = ct . W_proj + b_proj  (M=8192, N=512, K=1024)
// ===========================================================================
__global__ __launch_bounds__(256, 1) void k_proj_tc(const float* __restrict__ bp,
                                                    float* __restrict__ outp)
{
    extern __shared__ __align__(1024) char smem[];
    const uint32_t smem_base = smem_to_u32(smem);
    const int tid = threadIdx.x, lane = tid & 31, wid = tid >> 5;
    const int m0 = blockIdx.y * 128, n0 = blockIdx.x * 128;

    float acc[4][4][4];
    gemm_mainloop(smem_base, g_ct_hi + (size_t)m0 * HID, g_ct_lo + (size_t)m0 * HID, HID,
                  g_wt_hi + (size_t)n0 * HID, g_wt_lo + (size_t)n0 * HID, HID,
                  HID / BK, tid, acc);

    const int wm = wid & 1, wn = wid >> 1;
    const int g = lane >> 2, tq = lane & 3;
    #pragma unroll
    for (int mi = 0; mi < 4; mi++) {
        const int r0 = m0 + wm * 64 + mi * 16 + g;
        #pragma unroll
        for (int ni = 0; ni < 4; ni++) {
            const int col = n0 + wn * 32 + ni * 8 + tq * 2;
            const float2 bb = *reinterpret_cast<const float2*>(&bp[col]);
            float2 p;
            p.x = acc[mi][ni][0] + bb.x; p.y = acc[mi][ni][1] + bb.y;
            *reinterpret_cast<float2*>(&outp[(size_t)r0 * OUT + col]) = p;
            p.x = acc[mi][ni][2] + bb.x; p.y = acc[mi][ni][3] + bb.y;
            *reinterpret_cast<float2*>(&outp[(size_t)(r0 + 8) * OUT + col]) = p;
        }
    }
}

// ===========================================================================
// Prep kernels
// ===========================================================================
__global__ __launch_bounds__(256)
void k_split(const float* __restrict__ in, __nv_bfloat16* __restrict__ oh,
             __nv_bfloat16* __restrict__ ol, int n4)
{
    const int i = blockIdx.x * 256 + threadIdx.x;
    if (i >= n4) return;
    const float4 v = reinterpret_cast<const float4*>(in)[i];
    float h0, l0, h1, l1, h2, l2, h3, l3;
    split1(v.x, h0, l0); split1(v.y, h1, l1);
    split1(v.z, h2, l2); split1(v.w, h3, l3);
    uint2 vh, vl;
    vh.x = pack2bf(h0, h1); vh.y = pack2bf(h2, h3);
    vl.x = pack2bf(l0, l1); vl.y = pack2bf(l2, l3);
    reinterpret_cast<uint2*>(oh)[i] = vh;
    reinterpret_cast<uint2*>(ol)[i] = vl;
}

// transpose [R][C] -> [C][R] with bf16 hi/lo split (batched via blockIdx.z)
__global__ __launch_bounds__(256)
void k_trans_split(const float* __restrict__ in, __nv_bfloat16* __restrict__ oh,
                   __nv_bfloat16* __restrict__ ol, int R, int C)
{
    __shared__ float t[32][33];
    const size_t boff = (size_t)blockIdx.z * R * C;
    in += boff; oh += boff; ol += boff;
    const int r0 = blockIdx.y * 32, c0 = blockIdx.x * 32;
    const int tx = threadIdx.x & 31, ty = threadIdx.x >> 5;   // 32 x 8
    #pragma unroll
    for (int i = 0; i < 4; i++)
        t[ty + i * 8][tx] = in[(size_t)(r0 + ty + i * 8) * C + c0 + tx];
    __syncthreads();
    #pragma unroll
    for (int i = 0; i < 4; i++) {
        const float v = t[tx][ty + i * 8];
        float hf, lf;
        split1(v, hf, lf);
        const size_t oidx = (size_t)(c0 + ty + i * 8) * R + r0 + tx;
        oh[oidx] = __float2bfloat16_rn(hf);
        ol[oidx] = __float2bfloat16_rn(lf);
    }
}

// lambda gate
__global__ __launch_bounds__(256)
void k_lambda(const float* __restrict__ ho, const float* __restrict__ Wl,
              const float* __restrict__ bl)
{
    const int row = blockIdx.x;
    const int t = threadIdx.x;
    const float4 xv = reinterpret_cast<const float4*>(ho + (size_t)row * HID)[t];
    const float4 wv = reinterpret_cast<const float4*>(Wl)[t];
    float s = xv.x * wv.x + xv.y * wv.y + xv.z * wv.z + xv.w * wv.w;
    #pragma unroll
    for (int o = 16; o > 0; o >>= 1) s += __shfl_xor_sync(0xFFFFFFFFu, s, o);
    __shared__ float sm[8];
    if ((t & 31) == 0) sm[t >> 5] = s;
    __syncthreads();
    if (t == 0) {
        float tot = 0.f;
        #pragma unroll
        for (int i = 0; i < 8; i++) tot += sm[i];
        tot += bl[0];
        g_lam[row] = 1.f / (1.f + expf(-tot));
    }
}

// row softmax over fp32 scores -> bf16 hi/lo attention
__global__ __launch_bounds__(256)
void k_softmax()
{
    const float* p = g_scores + (size_t)blockIdx.x * SEQ;
    __nv_bfloat16* aH = g_attn_hi + (size_t)blockIdx.x * SEQ;
    __nv_bfloat16* aL = g_attn_lo + (size_t)blockIdx.x * SEQ;
    const int t = threadIdx.x;
    float4 v0 = reinterpret_cast<const float4*>(p)[t];
    float4 v1 = reinterpret_cast<const float4*>(p)[t + 256];

    float m = fmaxf(fmaxf(fmaxf(v0.x, v0.y), fmaxf(v0.z, v0.w)),
                    fmaxf(fmaxf(v1.x, v1.y), fmaxf(v1.z, v1.w)));
    #pragma unroll
    for (int o = 16; o > 0; o >>= 1) m = fmaxf(m, __shfl_xor_sync(0xFFFFFFFFu, m, o));
    __shared__ float sm[8];
    if ((t & 31) == 0) sm[t >> 5] = m;
    __syncthreads();
    m = sm[0];
    #pragma unroll
    for (int i = 1; i < 8; i++) m = fmaxf(m, sm[i]);
    __syncthreads();

    v0.x = expf(v0.x - m); v0.y = expf(v0.y - m);
    v0.z = expf(v0.z - m); v0.w = expf(v0.w - m);
    v1.x = expf(v1.x - m); v1.y = expf(v1.y - m);
    v1.z = expf(v1.z - m); v1.w = expf(v1.w - m);

    float s = (v0.x + v0.y + v0.z + v0.w) + (v1.x + v1.y + v1.z + v1.w);
    #pragma unroll
    for (int o = 16; o > 0; o >>= 1) s += __shfl_xor_sync(0xFFFFFFFFu, s, o);
    if ((t & 31) == 0) sm[t >> 5] = s;
    __syncthreads();
    s = sm[0];
    #pragma unroll
    for (int i = 1; i < 8; i++) s += sm[i];
    const float inv = 1.f / s;

    float h0, l0, h1, l1, h2, l2, h3, l3;
    uint2 vh, vl;
    split1(v0.x * inv, h0, l0); split1(v0.y * inv, h1, l1);
    split1(v0.z * inv, h2, l2); split1(v0.w * inv, h3, l3);
    vh.x = pack2bf(h0, h1); vh.y = pack2bf(h2, h3);
    vl.x = pack2bf(l0, l1); vl.y = pack2bf(l2, l3);
    *reinterpret_cast<uint2*>(&aH[4 * t]) = vh;
    *reinterpret_cast<uint2*>(&aL[4 * t]) = vl;

    split1(v1.x * inv, h0, l0); split1(v1.y * inv, h1, l1);
    split1(v1.z * inv, h2, l2); split1(v1.w * inv, h3, l3);
    vh.x = pack2bf(h0, h1); vh.y = pack2bf(h2, h3);
    vl.x = pack2bf(l0, l1); vl.y = pack2bf(l2, l3);
    *reinterpret_cast<uint2*>(&aH[4 * (t + 256)]) = vh;
    *reinterpret_cast<uint2*>(&aL[4 * (t + 256)]) = vl;
}

// ===========================================================================
// Launch
// ===========================================================================
extern "C" void kernel_launch(void* const* d_in, const int* in_sizes, int n_in,
                              void* d_out, int out_size)
{
    const float* ho = (const float*)d_in[0];   // [4, 2048, 1024]
    const float* hi = (const float*)d_in[1];   // [4, 2048, 1024]
    const float* Wl = (const float*)d_in[2];   // [1024, 1]
    const float* bl = (const float*)d_in[3];   // [1]
    const float* Wp = (const float*)d_in[4];   // [1024, 512]
    const float* bp = (const float*)d_in[5];   // [512]
    float* outp = (float*)d_out;               // [4, 2048, 512]

    cudaFuncSetAttribute(k_scores_tc, cudaFuncAttributeMaxDynamicSharedMemorySize, SMEM_TOTAL);
    cudaFuncSetAttribute(k_attend_tc, cudaFuncAttributeMaxDynamicSharedMemorySize, SMEM_TOTAL);
    cudaFuncSetAttribute(k_proj_tc,   cudaFuncAttributeMaxDynamicSharedMemorySize, SMEM_TOTAL);

    __nv_bfloat16 *p_ho_hi, *p_ho_lo, *p_hi_hi, *p_hi_lo, *p_hiT_hi, *p_hiT_lo, *p_wt_hi, *p_wt_lo;
    cudaGetSymbolAddress((void**)&p_ho_hi,  g_ho_hi);
    cudaGetSymbolAddress((void**)&p_ho_lo,  g_ho_lo);
    cudaGetSymbolAddress((void**)&p_hi_hi,  g_hi_hi);
    cudaGetSymbolAddress((void**)&p_hi_lo,  g_hi_lo);
    cudaGetSymbolAddress((void**)&p_hiT_hi, g_hiT_hi);
    cudaGetSymbolAddress((void**)&p_hiT_lo, g_hiT_lo);
    cudaGetSymbolAddress((void**)&p_wt_hi,  g_wt_hi);
    cudaGetSymbolAddress((void**)&p_wt_lo,  g_wt_lo);

    const int n4 = BATCH * SEQ * HID / 4;

    // Prep: splits, transposes, gate
    k_split<<<(n4 + 255) / 256, 256>>>(ho, p_ho_hi, p_ho_lo, n4);
    k_split<<<(n4 + 255) / 256, 256>>>(hi, p_hi_hi, p_hi_lo, n4);
    {
        dim3 gt(HID / 32, SEQ / 32, BATCH);
        k_trans_split<<<gt, 256>>>(hi, p_hiT_hi, p_hiT_lo, SEQ, HID);
    }
    {
        dim3 gw(OUT / 32, HID / 32, 1);
        k_trans_split<<<gw, 256>>>(Wp, p_wt_hi, p_wt_lo, HID, OUT);
    }
    k_lambda<<<BATCH * SEQ, 256>>>(ho, Wl, bl);

    // GEMM1: scores
    {
        dim3 g(SEQ / 128, SEQ / 128, BATCH);   // 16 x 16 x 4
        k_scores_tc<<<g, 256, SMEM_TOTAL>>>();
    }
    // softmax -> bf16 attn splits
    k_softmax<<<BATCH * SEQ, 256>>>();
    // GEMM2: attend + gate -> ct splits
    {
        dim3 g(HID / 128, SEQ / 128, BATCH);   // 8 x 16 x 4
        k_attend_tc<<<g, 256, SMEM_TOTAL>>>(ho);
    }
    // GEMM3: projection + bias
    {
        dim3 g(OUT / 128, (BATCH * SEQ) / 128, 1);   // 4 x 64
        k_proj_tc<<<g, 256, SMEM_TOTAL>>>(bp, outp);
    }
}

// round 9
// speedup vs baseline: 2.7943x; 1.2118x over previous
#include <cuda_runtime.h>
#include <cuda_bf16.h>
#include <math.h>
#include <stdint.h>

// Problem constants (fixed shapes: B=4, S=2048, H=1024, O=512)
#define BATCH 4
#define SEQ   2048
#define HID   1024
#define OUT   512

// ===========================================================================
// Device scratch
// ===========================================================================
__device__ float g_scores[(size_t)BATCH * SEQ * SEQ];            // 64 MB fp32
__device__ float g_lam[BATCH * SEQ];

__device__ __nv_bfloat16 g_ho_hi[(size_t)BATCH * SEQ * HID];
__device__ __nv_bfloat16 g_ho_lo[(size_t)BATCH * SEQ * HID];
__device__ __nv_bfloat16 g_hi_hi[(size_t)BATCH * SEQ * HID];
__device__ __nv_bfloat16 g_hi_lo[(size_t)BATCH * SEQ * HID];
__device__ __nv_bfloat16 g_hiT_hi[(size_t)BATCH * HID * SEQ];    // hi transposed
__device__ __nv_bfloat16 g_hiT_lo[(size_t)BATCH * HID * SEQ];
__device__ __nv_bfloat16 g_attn_hi[(size_t)BATCH * SEQ * SEQ];
__device__ __nv_bfloat16 g_attn_lo[(size_t)BATCH * SEQ * SEQ];
__device__ __nv_bfloat16 g_ct_hi[(size_t)BATCH * SEQ * HID];
__device__ __nv_bfloat16 g_ct_lo[(size_t)BATCH * SEQ * HID];
__device__ __nv_bfloat16 g_wt_hi[(size_t)OUT * HID];             // W_proj^T
__device__ __nv_bfloat16 g_wt_lo[(size_t)OUT * HID];

// ===========================================================================
// Low-level helpers (all sm_80+ PTX: compiles on compute_100)
// ===========================================================================
__device__ __forceinline__ uint32_t smem_to_u32(const void* p) {
    uint32_t a;
    asm("{ .reg .u64 t; cvta.to.shared.u64 t, %1; cvt.u32.u64 %0, t; }" : "=r"(a) : "l"(p));
    return a;
}
__device__ __forceinline__ uint32_t sw64(uint32_t o) { return o ^ ((o >> 3) & 0x30); }

__device__ __forceinline__ void cp16(uint32_t dst, const void* src) {
    asm volatile("cp.async.cg.shared.global [%0], [%1], 16;" :: "r"(dst), "l"(src));
}
#define CP_COMMIT() asm volatile("cp.async.commit_group;" ::: "memory")
#define CP_WAIT(n)  asm volatile("cp.async.wait_group %0;" :: "n"(n) : "memory")

__device__ __forceinline__ void ldsm4(uint32_t (&r)[4], uint32_t addr) {
    asm volatile("ldmatrix.sync.aligned.m8n8.x4.shared.b16 {%0,%1,%2,%3}, [%4];"
                 : "=r"(r[0]), "=r"(r[1]), "=r"(r[2]), "=r"(r[3]) : "r"(addr));
}
__device__ __forceinline__ void mma16816(float (&d)[4], const uint32_t a[4], const uint32_t b[2]) {
    asm volatile(
        "mma.sync.aligned.m16n8k16.row.col.f32.bf16.bf16.f32 "
        "{%0,%1,%2,%3},{%4,%5,%6,%7},{%8,%9},{%0,%1,%2,%3};"
        : "+f"(d[0]), "+f"(d[1]), "+f"(d[2]), "+f"(d[3])
        : "r"(a[0]), "r"(a[1]), "r"(a[2]), "r"(a[3]), "r"(b[0]), "r"(b[1]));
}

__device__ __forceinline__ uint32_t pack2bf(float a, float b) {
    __nv_bfloat162 t = __floats2bfloat162_rn(a, b);
    return *reinterpret_cast<uint32_t*>(&t);
}
__device__ __forceinline__ void split1(float x, float& hf, float& lf) {
    __nv_bfloat16 h = __float2bfloat16_rn(x);
    hf = __bfloat162float(h);
    lf = x - hf;
}

// ===========================================================================
// GEMM mainloop: CTA tile 128(M) x 128(N), BK=32, 2-stage cp.async pipeline,
// 64 KB smem -> 2 CTAs/SM for bubble hiding.
// 3-term compensated bf16: acc += Ah*Bh + Ah*Bl + Al*Bh (fp32 accum).
// A: [128 rows, K] K-contiguous; B: [128 n-rows, K] K-contiguous.
// ===========================================================================
#define BK          32
#define NSTAGE      2
#define TILE_BYTES  8192                   // 128 rows x 64B
#define STAGE_BYTES (4 * TILE_BYTES)       // Ah,Al,Bh,Bl = 32 KB
#define OFF_AHI     0
#define OFF_ALO     TILE_BYTES
#define OFF_BHI     (2 * TILE_BYTES)
#define OFF_BLO     (3 * TILE_BYTES)
#define SMEM_TOTAL  (NSTAGE * STAGE_BYTES) // 64 KB

__device__ __forceinline__ void load_stage(uint32_t smem_base, int s,
    const __nv_bfloat16* __restrict__ Ah, const __nv_bfloat16* __restrict__ Al, int ldA,
    const __nv_bfloat16* __restrict__ Bh, const __nv_bfloat16* __restrict__ Bl, int ldB,
    int k0, int tid)
{
    const uint32_t sb = smem_base + (uint32_t)s * STAGE_BYTES;
    #pragma unroll
    for (int i = 0; i < 2; i++) {
        const int idx = tid + i * 256;           // 0..511
        const int r = idx >> 2, c = idx & 3;     // row 0..127, 16B chunk 0..3
        const uint32_t so = sw64((uint32_t)((r << 6) | (c << 4)));
        const size_t ga = (size_t)r * ldA + k0 + c * 8;
        const size_t gb = (size_t)r * ldB + k0 + c * 8;
        cp16(sb + OFF_AHI + so, Ah + ga);
        cp16(sb + OFF_ALO + so, Al + ga);
        cp16(sb + OFF_BHI + so, Bh + gb);
        cp16(sb + OFF_BLO + so, Bl + gb);
    }
}

// acc[mi][ni][4]: warp tile 64(M) x 32(N); warps: wm = wid&1 (M), wn = wid>>1 (N)
__device__ __forceinline__ void gemm_mainloop(uint32_t smem_base,
    const __nv_bfloat16* __restrict__ Ah, const __nv_bfloat16* __restrict__ Al, int ldA,
    const __nv_bfloat16* __restrict__ Bh, const __nv_bfloat16* __restrict__ Bl, int ldB,
    int nchunks, int tid, float (&acc)[4][4][4])
{
    #pragma unroll
    for (int mi = 0; mi < 4; mi++)
        #pragma unroll
        for (int ni = 0; ni < 4; ni++)
            #pragma unroll
            for (int d = 0; d < 4; d++) acc[mi][ni][d] = 0.f;

    // prologue: prefetch stage 0
    load_stage(smem_base, 0, Ah, Al, ldA, Bh, Bl, ldB, 0, tid);
    CP_COMMIT();
    CP_WAIT(0);
    __syncthreads();

    const int lane = tid & 31, wid = tid >> 5;
    const int wm = wid & 1, wn = wid >> 1;
    const int quad = lane >> 3, lrow = lane & 7;
    // per-lane ldmatrix row/col-byte (within tile), before swizzle
    const uint32_t a_term = (uint32_t)((wm * 64 + (quad & 1) * 8 + lrow) << 6) + ((quad >> 1) << 4);
    const uint32_t b_term = (uint32_t)((wn * 32 + (quad >> 1) * 8 + lrow) << 6) + ((quad & 1) << 4);

    for (int c = 0; c < nchunks; c++) {
        const uint32_t sb = smem_base + (uint32_t)(c & 1) * STAGE_BYTES;

        // prefetch chunk c+1 into the other stage; it overlaps compute(c).
        // Target stage held chunk c-1, fully consumed before the barrier at
        // the end of iteration c-1 -> write-safe.
        const int cp = c + 1;
        if (cp < nchunks)
            load_stage(smem_base, cp & 1, Ah, Al, ldA, Bh, Bl, ldB, cp * BK, tid);
        CP_COMMIT();

        #pragma unroll
        for (int ks = 0; ks < 2; ks++) {
            const uint32_t koff = (uint32_t)ks * 32;
            uint32_t Ahf[4][4], Alf[4][4];
            #pragma unroll
            for (int mi = 0; mi < 4; mi++) {
                const uint32_t off = sw64(a_term + (uint32_t)(mi << 10) + koff);
                ldsm4(Ahf[mi], sb + OFF_AHI + off);
                ldsm4(Alf[mi], sb + OFF_ALO + off);
            }
            uint32_t Bhf[2][4], Blf[2][4];
            #pragma unroll
            for (int bi = 0; bi < 2; bi++) {
                const uint32_t off = sw64(b_term + (uint32_t)(bi << 10) + koff);
                ldsm4(Bhf[bi], sb + OFF_BHI + off);
                ldsm4(Blf[bi], sb + OFF_BLO + off);
            }
            #pragma unroll
            for (int mi = 0; mi < 4; mi++)
                #pragma unroll
                for (int ni = 0; ni < 4; ni++) {
                    const uint32_t* bh = &Bhf[ni >> 1][(ni & 1) * 2];
                    const uint32_t* bl = &Blf[ni >> 1][(ni & 1) * 2];
                    mma16816(acc[mi][ni], Ahf[mi], bh);
                    mma16816(acc[mi][ni], Ahf[mi], bl);
                    mma16816(acc[mi][ni], Alf[mi], bh);
                }
        }
        CP_WAIT(0);        // chunk c+1 landed (overlapped with the MMAs above)
        __syncthreads();
    }
}

// ===========================================================================
// GEMM 1: scores = (1/32) * ho . hi^T   per batch (M=N=2048, K=1024)
// ===========================================================================
__global__ __launch_bounds__(256, 2) void k_scores_tc()
{
    extern __shared__ __align__(1024) char smem[];
    const uint32_t smem_base = smem_to_u32(smem);
    const int tid = threadIdx.x, lane = tid & 31, wid = tid >> 5;
    const int b = blockIdx.z, m0 = blockIdx.y * 128, n0 = blockIdx.x * 128;

    const size_t ab = ((size_t)b * SEQ + m0) * HID;
    const size_t bb = ((size_t)b * SEQ + n0) * HID;
    float acc[4][4][4];
    gemm_mainloop(smem_base, g_ho_hi + ab, g_ho_lo + ab, HID,
                  g_hi_hi + bb, g_hi_lo + bb, HID, HID / BK, tid, acc);

    float* C = g_scores + (size_t)b * SEQ * SEQ;
    const int wm = wid & 1, wn = wid >> 1;
    const int g = lane >> 2, tq = lane & 3;
    #pragma unroll
    for (int mi = 0; mi < 4; mi++) {
        const int r0 = m0 + wm * 64 + mi * 16 + g;
        #pragma unroll
        for (int ni = 0; ni < 4; ni++) {
            const int col = n0 + wn * 32 + ni * 8 + tq * 2;
            float2 p;
            p.x = acc[mi][ni][0] * 0.03125f; p.y = acc[mi][ni][1] * 0.03125f;
            *reinterpret_cast<float2*>(&C[(size_t)r0 * SEQ + col]) = p;
            p.x = acc[mi][ni][2] * 0.03125f; p.y = acc[mi][ni][3] * 0.03125f;
            *reinterpret_cast<float2*>(&C[(size_t)(r0 + 8) * SEQ + col]) = p;
        }
    }
}

// ===========================================================================
// GEMM 2: attended = attn . hi (via hiT) + fused gate -> ct (bf16 hi/lo)
//   per batch: M=2048, N=1024, K=2048
// ===========================================================================
__global__ __launch_bounds__(256, 2) void k_attend_tc(const float* __restrict__ ho)
{
    extern __shared__ __align__(1024) char smem[];
    const uint32_t smem_base = smem_to_u32(smem);
    const int tid = threadIdx.x, lane = tid & 31, wid = tid >> 5;
    const int b = blockIdx.z, m0 = blockIdx.y * 128, n0 = blockIdx.x * 128;

    const size_t ab = (size_t)b * SEQ * SEQ + (size_t)m0 * SEQ;
    const size_t bb = (size_t)b * HID * SEQ + (size_t)n0 * SEQ;
    float acc[4][4][4];
    gemm_mainloop(smem_base, g_attn_hi + ab, g_attn_lo + ab, SEQ,
                  g_hiT_hi + bb, g_hiT_lo + bb, SEQ, SEQ / BK, tid, acc);

    const int wm = wid & 1, wn = wid >> 1;
    const int g = lane >> 2, tq = lane & 3;
    const float* lamB = g_lam + b * SEQ;
    #pragma unroll
    for (int mi = 0; mi < 4; mi++) {
        const int r0 = m0 + wm * 64 + mi * 16 + g;
        const int r1 = r0 + 8;
        const float l0 = lamB[r0], gl0 = 1.f - l0;
        const float l1 = lamB[r1], gl1 = 1.f - l1;
        const float* hoR0 = ho + ((size_t)b * SEQ + r0) * HID;
        const float* hoR1 = ho + ((size_t)b * SEQ + r1) * HID;
        __nv_bfloat16* CH0 = g_ct_hi + ((size_t)b * SEQ + r0) * HID;
        __nv_bfloat16* CL0 = g_ct_lo + ((size_t)b * SEQ + r0) * HID;
        __nv_bfloat16* CH1 = g_ct_hi + ((size_t)b * SEQ + r1) * HID;
        __nv_bfloat16* CL1 = g_ct_lo + ((size_t)b * SEQ + r1) * HID;
        #pragma unroll
        for (int ni = 0; ni < 4; ni++) {
            const int col = n0 + wn * 32 + ni * 8 + tq * 2;
            {
                const float2 h = *reinterpret_cast<const float2*>(&hoR0[col]);
                const float c0 = l0 * h.x + gl0 * acc[mi][ni][0];
                const float c1 = l0 * h.y + gl0 * acc[mi][ni][1];
                float h0, lo0, h1, lo1;
                split1(c0, h0, lo0); split1(c1, h1, lo1);
                *reinterpret_cast<uint32_t*>(&CH0[col]) = pack2bf(h0, h1);
                *reinterpret_cast<uint32_t*>(&CL0[col]) = pack2bf(lo0, lo1);
            }
            {
                const float2 h = *reinterpret_cast<const float2*>(&hoR1[col]);
                const float c0 = l1 * h.x + gl1 * acc[mi][ni][2];
                const float c1 = l1 * h.y + gl1 * acc[mi][ni][3];
                float h0, lo0, h1, lo1;
                split1(c0, h0, lo0); split1(c1, h1, lo1);
                *reinterpret_cast<uint32_t*>(&CH1[col]) = pack2bf(h0, h1);
                *reinterpret_cast<uint32_t*>(&CL1[col]) = pack2bf(lo0, lo1);
            }
        }
    }
}

// ===========================================================================
// GEMM 3: out = ct . W_proj + b_proj  (M=8192, N=512, K=1024)
// ===========================================================================
__global__ __launch_bounds__(256, 2) void k_proj_tc(const float* __restrict__ bp,
                                                    float* __restrict__ outp)
{
    extern __shared__ __align__(1024) char smem[];
    const uint32_t smem_base = smem_to_u32(smem);
    const int tid = threadIdx.x, lane = tid & 31, wid = tid >> 5;
    const int m0 = blockIdx.y * 128, n0 = blockIdx.x * 128;

    float acc[4][4][4];
    gemm_mainloop(smem_base, g_ct_hi + (size_t)m0 * HID, g_ct_lo + (size_t)m0 * HID, HID,
                  g_wt_hi + (size_t)n0 * HID, g_wt_lo + (size_t)n0 * HID, HID,
                  HID / BK, tid, acc);

    const int wm = wid & 1, wn = wid >> 1;
    const int g = lane >> 2, tq = lane & 3;
    #pragma unroll
    for (int mi = 0; mi < 4; mi++) {
        const int r0 = m0 + wm * 64 + mi * 16 + g;
        #pragma unroll
        for (int ni = 0; ni < 4; ni++) {
            const int col = n0 + wn * 32 + ni * 8 + tq * 2;
            const float2 bb = *reinterpret_cast<const float2*>(&bp[col]);
            float2 p;
            p.x = acc[mi][ni][0] + bb.x; p.y = acc[mi][ni][1] + bb.y;
            *reinterpret_cast<float2*>(&outp[(size_t)r0 * OUT + col]) = p;
            p.x = acc[mi][ni][2] + bb.x; p.y = acc[mi][ni][3] + bb.y;
            *reinterpret_cast<float2*>(&outp[(size_t)(r0 + 8) * OUT + col]) = p;
        }
    }
}

// ===========================================================================
// Prep kernels
// ===========================================================================
__global__ __launch_bounds__(256)
void k_split(const float* __restrict__ in, __nv_bfloat16* __restrict__ oh,
             __nv_bfloat16* __restrict__ ol, int n4)
{
    const int i = blockIdx.x * 256 + threadIdx.x;
    if (i >= n4) return;
    const float4 v = reinterpret_cast<const float4*>(in)[i];
    float h0, l0, h1, l1, h2, l2, h3, l3;
    split1(v.x, h0, l0); split1(v.y, h1, l1);
    split1(v.z, h2, l2); split1(v.w, h3, l3);
    uint2 vh, vl;
    vh.x = pack2bf(h0, h1); vh.y = pack2bf(h2, h3);
    vl.x = pack2bf(l0, l1); vl.y = pack2bf(l2, l3);
    reinterpret_cast<uint2*>(oh)[i] = vh;
    reinterpret_cast<uint2*>(ol)[i] = vl;
}

// transpose [R][C] -> [C][R] with bf16 hi/lo split (batched via blockIdx.z)
__global__ __launch_bounds__(256)
void k_trans_split(const float* __restrict__ in, __nv_bfloat16* __restrict__ oh,
                   __nv_bfloat16* __restrict__ ol, int R, int C)
{
    __shared__ float t[32][33];
    const size_t boff = (size_t)blockIdx.z * R * C;
    in += boff; oh += boff; ol += boff;
    const int r0 = blockIdx.y * 32, c0 = blockIdx.x * 32;
    const int tx = threadIdx.x & 31, ty = threadIdx.x >> 5;   // 32 x 8
    #pragma unroll
    for (int i = 0; i < 4; i++)
        t[ty + i * 8][tx] = in[(size_t)(r0 + ty + i * 8) * C + c0 + tx];
    __syncthreads();
    #pragma unroll
    for (int i = 0; i < 4; i++) {
        const float v = t[tx][ty + i * 8];
        float hf, lf;
        split1(v, hf, lf);
        const size_t oidx = (size_t)(c0 + ty + i * 8) * R + r0 + tx;
        oh[oidx] = __float2bfloat16_rn(hf);
        ol[oidx] = __float2bfloat16_rn(lf);
    }
}

// lambda gate
__global__ __launch_bounds__(256)
void k_lambda(const float* __restrict__ ho, const float* __restrict__ Wl,
              const float* __restrict__ bl)
{
    const int row = blockIdx.x;
    const int t = threadIdx.x;
    const float4 xv = reinterpret_cast<const float4*>(ho + (size_t)row * HID)[t];
    const float4 wv = reinterpret_cast<const float4*>(Wl)[t];
    float s = xv.x * wv.x + xv.y * wv.y + xv.z * wv.z + xv.w * wv.w;
    #pragma unroll
    for (int o = 16; o > 0; o >>= 1) s += __shfl_xor_sync(0xFFFFFFFFu, s, o);
    __shared__ float sm[8];
    if ((t & 31) == 0) sm[t >> 5] = s;
    __syncthreads();
    if (t == 0) {
        float tot = 0.f;
        #pragma unroll
        for (int i = 0; i < 8; i++) tot += sm[i];
        tot += bl[0];
        g_lam[row] = 1.f / (1.f + expf(-tot));
    }
}

// row softmax over fp32 scores -> bf16 hi/lo attention
__global__ __launch_bounds__(256)
void k_softmax()
{
    const float* p = g_scores + (size_t)blockIdx.x * SEQ;
    __nv_bfloat16* aH = g_attn_hi + (size_t)blockIdx.x * SEQ;
    __nv_bfloat16* aL = g_attn_lo + (size_t)blockIdx.x * SEQ;
    const int t = threadIdx.x;
    float4 v0 = reinterpret_cast<const float4*>(p)[t];
    float4 v1 = reinterpret_cast<const float4*>(p)[t + 256];

    float m = fmaxf(fmaxf(fmaxf(v0.x, v0.y), fmaxf(v0.z, v0.w)),
                    fmaxf(fmaxf(v1.x, v1.y), fmaxf(v1.z, v1.w)));
    #pragma unroll
    for (int o = 16; o > 0; o >>= 1) m = fmaxf(m, __shfl_xor_sync(0xFFFFFFFFu, m, o));
    __shared__ float sm[8];
    if ((t & 31) == 0) sm[t >> 5] = m;
    __syncthreads();
    m = sm[0];
    #pragma unroll
    for (int i = 1; i < 8; i++) m = fmaxf(m, sm[i]);
    __syncthreads();

    v0.x = expf(v0.x - m); v0.y = expf(v0.y - m);
    v0.z = expf(v0.z - m); v0.w = expf(v0.w - m);
    v1.x = expf(v1.x - m); v1.y = expf(v1.y - m);
    v1.z = expf(v1.z - m); v1.w = expf(v1.w - m);

    float s = (v0.x + v0.y + v0.z + v0.w) + (v1.x + v1.y + v1.z + v1.w);
    #pragma unroll
    for (int o = 16; o > 0; o >>= 1) s += __shfl_xor_sync(0xFFFFFFFFu, s, o);
    if ((t & 31) == 0) sm[t >> 5] = s;
    __syncthreads();
    s = sm[0];
    #pragma unroll
    for (int i = 1; i < 8; i++) s += sm[i];
    const float inv = 1.f / s;

    float h0, l0, h1, l1, h2, l2, h3, l3;
    uint2 vh, vl;
    split1(v0.x * inv, h0, l0); split1(v0.y * inv, h1, l1);
    split1(v0.z * inv, h2, l2); split1(v0.w * inv, h3, l3);
    vh.x = pack2bf(h0, h1); vh.y = pack2bf(h2, h3);
    vl.x = pack2bf(l0, l1); vl.y = pack2bf(l2, l3);
    *reinterpret_cast<uint2*>(&aH[4 * t]) = vh;
    *reinterpret_cast<uint2*>(&aL[4 * t]) = vl;

    split1(v1.x * inv, h0, l0); split1(v1.y * inv, h1, l1);
    split1(v1.z * inv, h2, l2); split1(v1.w * inv, h3, l3);
    vh.x = pack2bf(h0, h1); vh.y = pack2bf(h2, h3);
    vl.x = pack2bf(l0, l1); vl.y = pack2bf(l2, l3);
    *reinterpret_cast<uint2*>(&aH[4 * (t + 256)]) = vh;
    *reinterpret_cast<uint2*>(&aL[4 * (t + 256)]) = vl;
}

// ===========================================================================
// Launch
// ===========================================================================
extern "C" void kernel_launch(void* const* d_in, const int* in_sizes, int n_in,
                              void* d_out, int out_size)
{
    const float* ho = (const float*)d_in[0];   // [4, 2048, 1024]
    const float* hi = (const float*)d_in[1];   // [4, 2048, 1024]
    const float* Wl = (const float*)d_in[2];   // [1024, 1]
    const float* bl = (const float*)d_in[3];   // [1]
    const float* Wp = (const float*)d_in[4];   // [1024, 512]
    const float* bp = (const float*)d_in[5];   // [512]
    float* outp = (float*)d_out;               // [4, 2048, 512]

    cudaFuncSetAttribute(k_scores_tc, cudaFuncAttributeMaxDynamicSharedMemorySize, SMEM_TOTAL);
    cudaFuncSetAttribute(k_attend_tc, cudaFuncAttributeMaxDynamicSharedMemorySize, SMEM_TOTAL);
    cudaFuncSetAttribute(k_proj_tc,   cudaFuncAttributeMaxDynamicSharedMemorySize, SMEM_TOTAL);

    __nv_bfloat16 *p_ho_hi, *p_ho_lo, *p_hi_hi, *p_hi_lo, *p_hiT_hi, *p_hiT_lo, *p_wt_hi, *p_wt_lo;
    cudaGetSymbolAddress((void**)&p_ho_hi,  g_ho_hi);
    cudaGetSymbolAddress((void**)&p_ho_lo,  g_ho_lo);
    cudaGetSymbolAddress((void**)&p_hi_hi,  g_hi_hi);
    cudaGetSymbolAddress((void**)&p_hi_lo,  g_hi_lo);
    cudaGetSymbolAddress((void**)&p_hiT_hi, g_hiT_hi);
    cudaGetSymbolAddress((void**)&p_hiT_lo, g_hiT_lo);
    cudaGetSymbolAddress((void**)&p_wt_hi,  g_wt_hi);
    cudaGetSymbolAddress((void**)&p_wt_lo,  g_wt_lo);

    const int n4 = BATCH * SEQ * HID / 4;

    // Prep: splits, transposes, gate
    k_split<<<(n4 + 255) / 256, 256>>>(ho, p_ho_hi, p_ho_lo, n4);
    k_split<<<(n4 + 255) / 256, 256>>>(hi, p_hi_hi, p_hi_lo, n4);
    {
        dim3 gt(HID / 32, SEQ / 32, BATCH);
        k_trans_split<<<gt, 256>>>(hi, p_hiT_hi, p_hiT_lo, SEQ, HID);
    }
    {
        dim3 gw(OUT / 32, HID / 32, 1);
        k_trans_split<<<gw, 256>>>(Wp, p_wt_hi, p_wt_lo, HID, OUT);
    }
    k_lambda<<<BATCH * SEQ, 256>>>(ho, Wl, bl);

    // GEMM1: scores
    {
        dim3 g(SEQ / 128, SEQ / 128, BATCH);   // 16 x 16 x 4
        k_scores_tc<<<g, 256, SMEM_TOTAL>>>();
    }
    // softmax -> bf16 attn splits
    k_softmax<<<BATCH * SEQ, 256>>>();
    // GEMM2: attend + gate -> ct splits
    {
        dim3 g(HID / 128, SEQ / 128, BATCH);   // 8 x 16 x 4
        k_attend_tc<<<g, 256, SMEM_TOTAL>>>(ho);
    }
    // GEMM3: projection + bias
    {
        dim3 g(OUT / 128, (BATCH * SEQ) / 128, 1);   // 4 x 64
        k_proj_tc<<<g, 256, SMEM_TOTAL>>>(bp, outp);
    }
}